// round 2
// baseline (speedup 1.0000x reference)
#include <cuda_runtime.h>

// VDDecoder: 3-layer LSTM stack (H=2,2,1), locked dropout between layers.
// One thread per batch element. Layers software-pipelined with 1-step stagger
// so the three per-layer dependency chains in each iteration are independent.
// Transcendentals via ex2.approx + fdividef (rcp.approx): rel err ~1e-6.

__device__ __forceinline__ float fex2(float x) {
    float r;
    asm("ex2.approx.f32 %0, %1;" : "=f"(r) : "f"(x));
    return r;
}

__device__ __forceinline__ float fsig(float x) {
    // 1 / (1 + exp(-x)). Large |x| safe: exp->inf => 0, exp->0 => 1.
    float E = fex2(x * -1.4426950408889634f);
    return __fdividef(1.0f, 1.0f + E);
}

__device__ __forceinline__ float ftan(float x) {
    // tanh(x) = 1 - 2/(1 + exp(2x)). Large x: exp->inf => 1; large -x: => -1.
    float E = fex2(x * 2.8853900817779268f);
    return 1.0f - __fdividef(2.0f, 1.0f + E);
}

extern "C" __global__ void __launch_bounds__(64, 1)
vdlstm_kernel(const float* __restrict__ x,
              const float* __restrict__ W1ih, const float* __restrict__ W1hh,
              const float* __restrict__ b1,   const float* __restrict__ m1,
              const float* __restrict__ W2ih, const float* __restrict__ W2hh,
              const float* __restrict__ b2,   const float* __restrict__ m2,
              const float* __restrict__ W3ih, const float* __restrict__ W3hh,
              const float* __restrict__ b3,   const float* __restrict__ m3,
              float* __restrict__ out, int T, int B)
{
    int b = blockIdx.x * blockDim.x + threadIdx.x;
    if (b >= B) return;

    // ---- load all weights into registers (tiny) ----
    float w1i[8], w1h[16], bb1[8];
    float w2i[16], w2h[16], bb2[8];
    float w3i[8], w3h[4], bb3[4];
#pragma unroll
    for (int k = 0; k < 8; k++)  w1i[k] = W1ih[k];
#pragma unroll
    for (int k = 0; k < 16; k++) w1h[k] = W1hh[k];
#pragma unroll
    for (int k = 0; k < 8; k++)  bb1[k] = b1[k];
#pragma unroll
    for (int k = 0; k < 16; k++) w2i[k] = W2ih[k];
#pragma unroll
    for (int k = 0; k < 16; k++) w2h[k] = W2hh[k];
#pragma unroll
    for (int k = 0; k < 8; k++)  bb2[k] = b2[k];
#pragma unroll
    for (int k = 0; k < 8; k++)  w3i[k] = W3ih[k];
#pragma unroll
    for (int k = 0; k < 4; k++)  w3h[k] = W3hh[k];
#pragma unroll
    for (int k = 0; k < 4; k++)  bb3[k] = b3[k];

    const float m10 = m1[2 * b + 0], m11 = m1[2 * b + 1];
    const float m20 = m2[2 * b + 0], m21 = m2[2 * b + 1];
    const float m30 = m3[b];

    // ---- state ----
    float h10 = 0.f, h11 = 0.f, c10 = 0.f, c11 = 0.f;
    float h20 = 0.f, h21 = 0.f, c20 = 0.f, c21 = 0.f;
    float h3 = 0.f,  c3 = 0.f;
    float y10 = 0.f, y11 = 0.f;   // masked layer-1 output (input to layer 2)
    float y20 = 0.f, y21 = 0.f;   // masked layer-2 output (input to layer 3)

    // gate row order (torch): rows [0,1]=i, [2,3]=f, [4,5]=g, [6,7]=o
    auto step1 = [&](float xt) {
        float g0 = fmaf(xt, w1i[0], fmaf(h10, w1h[0],  fmaf(h11, w1h[1],  bb1[0])));
        float g1 = fmaf(xt, w1i[1], fmaf(h10, w1h[2],  fmaf(h11, w1h[3],  bb1[1])));
        float g2 = fmaf(xt, w1i[2], fmaf(h10, w1h[4],  fmaf(h11, w1h[5],  bb1[2])));
        float g3 = fmaf(xt, w1i[3], fmaf(h10, w1h[6],  fmaf(h11, w1h[7],  bb1[3])));
        float g4 = fmaf(xt, w1i[4], fmaf(h10, w1h[8],  fmaf(h11, w1h[9],  bb1[4])));
        float g5 = fmaf(xt, w1i[5], fmaf(h10, w1h[10], fmaf(h11, w1h[11], bb1[5])));
        float g6 = fmaf(xt, w1i[6], fmaf(h10, w1h[12], fmaf(h11, w1h[13], bb1[6])));
        float g7 = fmaf(xt, w1i[7], fmaf(h10, w1h[14], fmaf(h11, w1h[15], bb1[7])));
        float i0 = fsig(g0), i1 = fsig(g1);
        float f0 = fsig(g2), f1 = fsig(g3);
        float t0 = ftan(g4), t1 = ftan(g5);
        float o0 = fsig(g6), o1 = fsig(g7);
        c10 = fmaf(f0, c10, i0 * t0);
        c11 = fmaf(f1, c11, i1 * t1);
        h10 = o0 * ftan(c10);
        h11 = o1 * ftan(c11);
        y10 = h10 * m10;
        y11 = h11 * m11;
    };

    auto step2 = [&](float a0, float a1) {
        float g0 = fmaf(a0, w2i[0],  fmaf(a1, w2i[1],  fmaf(h20, w2h[0],  fmaf(h21, w2h[1],  bb2[0]))));
        float g1 = fmaf(a0, w2i[2],  fmaf(a1, w2i[3],  fmaf(h20, w2h[2],  fmaf(h21, w2h[3],  bb2[1]))));
        float g2 = fmaf(a0, w2i[4],  fmaf(a1, w2i[5],  fmaf(h20, w2h[4],  fmaf(h21, w2h[5],  bb2[2]))));
        float g3 = fmaf(a0, w2i[6],  fmaf(a1, w2i[7],  fmaf(h20, w2h[6],  fmaf(h21, w2h[7],  bb2[3]))));
        float g4 = fmaf(a0, w2i[8],  fmaf(a1, w2i[9],  fmaf(h20, w2h[8],  fmaf(h21, w2h[9],  bb2[4]))));
        float g5 = fmaf(a0, w2i[10], fmaf(a1, w2i[11], fmaf(h20, w2h[10], fmaf(h21, w2h[11], bb2[5]))));
        float g6 = fmaf(a0, w2i[12], fmaf(a1, w2i[13], fmaf(h20, w2h[12], fmaf(h21, w2h[13], bb2[6]))));
        float g7 = fmaf(a0, w2i[14], fmaf(a1, w2i[15], fmaf(h20, w2h[14], fmaf(h21, w2h[15], bb2[7]))));
        float i0 = fsig(g0), i1 = fsig(g1);
        float f0 = fsig(g2), f1 = fsig(g3);
        float t0 = ftan(g4), t1 = ftan(g5);
        float o0 = fsig(g6), o1 = fsig(g7);
        c20 = fmaf(f0, c20, i0 * t0);
        c21 = fmaf(f1, c21, i1 * t1);
        h20 = o0 * ftan(c20);
        h21 = o1 * ftan(c21);
        y20 = h20 * m20;
        y21 = h21 * m21;
    };

    auto step3 = [&](float a0, float a1) -> float {
        float g0 = fmaf(a0, w3i[0], fmaf(a1, w3i[1], fmaf(h3, w3h[0], bb3[0])));
        float g1 = fmaf(a0, w3i[2], fmaf(a1, w3i[3], fmaf(h3, w3h[1], bb3[1])));
        float g2 = fmaf(a0, w3i[4], fmaf(a1, w3i[5], fmaf(h3, w3h[2], bb3[2])));
        float g3 = fmaf(a0, w3i[6], fmaf(a1, w3i[7], fmaf(h3, w3h[3], bb3[3])));
        float ig = fsig(g0), fg = fsig(g1), gg = ftan(g2), og = fsig(g3);
        c3 = fmaf(fg, c3, ig * gg);
        h3 = og * ftan(c3);
        return h3 * m30;
    };

    const float* xp = x + b;
    float* op = out + b;
    const long long Bs = (long long)B;

    // ---- pipeline prologue ----
    // u = 0: layer1 only
    step1(xp[0]);
    // u = 1: layer1 + layer2
    {
        float a0 = y10, a1 = y11;
        step1(xp[Bs]);
        step2(a0, a1);
    }

    // ---- steady state: u = 2 .. T-1; layer1(u), layer2(u-1), layer3(u-2) ----
    // x prefetch regs hold x[u..u+3]
    float xa = xp[2 * Bs], xb = xp[3 * Bs], xc = xp[4 * Bs], xd = xp[5 * Bs];

#define PIPE_SUB(XREG, OFF, ROFF)                                              \
    {                                                                          \
        float a20 = y10, a21 = y11, a30 = y20, a31 = y21;                      \
        float nx = ((u + (ROFF)) < T) ? xp[(long long)(u + (ROFF)) * Bs] : 0.f;\
        step1(XREG);                                                           \
        step2(a20, a21);                                                       \
        op[(long long)(u + (OFF) - 2) * Bs] = step3(a30, a31);                 \
        XREG = nx;                                                             \
    }

    int u = 2;
    for (; u + 3 < T; u += 4) {
        PIPE_SUB(xa, 0, 4)
        PIPE_SUB(xb, 1, 5)
        PIPE_SUB(xc, 2, 6)
        PIPE_SUB(xd, 3, 7)
    }
    for (; u < T; ++u) {
        float a20 = y10, a21 = y11, a30 = y20, a31 = y21;
        step1(xa);
        step2(a20, a21);
        op[(long long)(u - 2) * Bs] = step3(a30, a31);
        xa = xb; xb = xc; xc = xd;
    }
#undef PIPE_SUB

    // ---- epilogue ----
    // u = T: layer2 + layer3
    {
        float a30 = y20, a31 = y21;
        step2(y10, y11);
        op[(long long)(T - 2) * Bs] = step3(a30, a31);
    }
    // u = T+1: layer3 only
    op[(long long)(T - 1) * Bs] = step3(y20, y21);
}

extern "C" void kernel_launch(void* const* d_in, const int* in_sizes, int n_in,
                              void* d_out, int out_size)
{
    const float* x    = (const float*)d_in[0];
    const float* W1ih = (const float*)d_in[1];
    const float* W1hh = (const float*)d_in[2];
    const float* b1   = (const float*)d_in[3];
    const float* m1   = (const float*)d_in[4];
    const float* W2ih = (const float*)d_in[5];
    const float* W2hh = (const float*)d_in[6];
    const float* b2   = (const float*)d_in[7];
    const float* m2   = (const float*)d_in[8];
    const float* W3ih = (const float*)d_in[9];
    const float* W3hh = (const float*)d_in[10];
    const float* b3   = (const float*)d_in[11];
    const float* m3   = (const float*)d_in[12];

    int B = in_sizes[12];            // m3 is [B]
    int T = in_sizes[0] / B;         // x is [T, B, 1]

    int threads = 64;
    int blocks = (B + threads - 1) / threads;
    vdlstm_kernel<<<blocks, threads>>>(x, W1ih, W1hh, b1, m1,
                                       W2ih, W2hh, b2, m2,
                                       W3ih, W3hh, b3, m3,
                                       (float*)d_out, T, B);
}

// round 3
// speedup vs baseline: 1.5441x; 1.5441x over previous
#include <cuda_runtime.h>

// VDDecoder: 3-layer LSTM stack (H=2,2,1), locked dropout between layers.
// One thread per batch element; layers software-pipelined with 1-step stagger.
// Activations via single-MUFU tanh.approx; sigmoid rows pre-scaled by 0.5 so
// sigmoid(g) = 0.5*tanh(g') + 0.5 with g' built directly from scaled weights.

__device__ __forceinline__ float ftanh(float x) {
    float r;
    asm("tanh.approx.f32 %0, %1;" : "=f"(r) : "f"(x));
    return r;
}

// g was computed with weights/bias pre-scaled by 0.5 => returns sigmoid(2g) = sigmoid(orig)
__device__ __forceinline__ float fsigp(float gh) {
    return fmaf(ftanh(gh), 0.5f, 0.5f);
}

extern "C" __global__ void __launch_bounds__(64, 1)
vdlstm_kernel(const float* __restrict__ x,
              const float* __restrict__ W1ih, const float* __restrict__ W1hh,
              const float* __restrict__ b1,   const float* __restrict__ m1,
              const float* __restrict__ W2ih, const float* __restrict__ W2hh,
              const float* __restrict__ b2,   const float* __restrict__ m2,
              const float* __restrict__ W3ih, const float* __restrict__ W3hh,
              const float* __restrict__ b3,   const float* __restrict__ m3,
              float* __restrict__ out, int T, int B)
{
    int b = blockIdx.x * blockDim.x + threadIdx.x;
    if (b >= B) return;

    // ---- load all weights into registers; pre-scale sigmoid rows by 0.5 ----
    // torch gate order, H=2: rows 0,1=i  2,3=f  4,5=g  6,7=o  -> scale all but rows 4,5
    // layer3 H=1: rows 0=i 1=f 2=g 3=o -> scale all but row 2
    float w1i[8], w1h[16], bb1[8];
    float w2i[16], w2h[16], bb2[8];
    float w3i[8], w3h[4], bb3[4];
#pragma unroll
    for (int k = 0; k < 8; k++) {
        float s = (k == 4 || k == 5) ? 1.0f : 0.5f;
        w1i[k] = W1ih[k] * s;
        w1h[2 * k]     = W1hh[2 * k] * s;
        w1h[2 * k + 1] = W1hh[2 * k + 1] * s;
        bb1[k] = b1[k] * s;
    }
#pragma unroll
    for (int k = 0; k < 8; k++) {
        float s = (k == 4 || k == 5) ? 1.0f : 0.5f;
        w2i[2 * k]     = W2ih[2 * k] * s;
        w2i[2 * k + 1] = W2ih[2 * k + 1] * s;
        w2h[2 * k]     = W2hh[2 * k] * s;
        w2h[2 * k + 1] = W2hh[2 * k + 1] * s;
        bb2[k] = b2[k] * s;
    }
#pragma unroll
    for (int k = 0; k < 4; k++) {
        float s = (k == 2) ? 1.0f : 0.5f;
        w3i[2 * k]     = W3ih[2 * k] * s;
        w3i[2 * k + 1] = W3ih[2 * k + 1] * s;
        w3h[k] = W3hh[k] * s;
        bb3[k] = b3[k] * s;
    }

    const float m10 = m1[2 * b + 0], m11 = m1[2 * b + 1];
    const float m20 = m2[2 * b + 0], m21 = m2[2 * b + 1];
    const float m30 = m3[b];

    // ---- state ----
    float h10 = 0.f, h11 = 0.f, c10 = 0.f, c11 = 0.f;
    float h20 = 0.f, h21 = 0.f, c20 = 0.f, c21 = 0.f;
    float h3 = 0.f,  c3 = 0.f;
    float y10 = 0.f, y11 = 0.f;   // masked layer-1 output (input to layer 2)
    float y20 = 0.f, y21 = 0.f;   // masked layer-2 output (input to layer 3)

    auto step1 = [&](float xt) {
        float g0 = fmaf(xt, w1i[0], fmaf(h10, w1h[0],  fmaf(h11, w1h[1],  bb1[0])));
        float g1 = fmaf(xt, w1i[1], fmaf(h10, w1h[2],  fmaf(h11, w1h[3],  bb1[1])));
        float g2 = fmaf(xt, w1i[2], fmaf(h10, w1h[4],  fmaf(h11, w1h[5],  bb1[2])));
        float g3 = fmaf(xt, w1i[3], fmaf(h10, w1h[6],  fmaf(h11, w1h[7],  bb1[3])));
        float g4 = fmaf(xt, w1i[4], fmaf(h10, w1h[8],  fmaf(h11, w1h[9],  bb1[4])));
        float g5 = fmaf(xt, w1i[5], fmaf(h10, w1h[10], fmaf(h11, w1h[11], bb1[5])));
        float g6 = fmaf(xt, w1i[6], fmaf(h10, w1h[12], fmaf(h11, w1h[13], bb1[6])));
        float g7 = fmaf(xt, w1i[7], fmaf(h10, w1h[14], fmaf(h11, w1h[15], bb1[7])));
        float i0 = fsigp(g0), i1 = fsigp(g1);
        float f0 = fsigp(g2), f1 = fsigp(g3);
        float t0 = ftanh(g4), t1 = ftanh(g5);
        float o0 = fsigp(g6), o1 = fsigp(g7);
        c10 = fmaf(f0, c10, i0 * t0);
        c11 = fmaf(f1, c11, i1 * t1);
        h10 = o0 * ftanh(c10);
        h11 = o1 * ftanh(c11);
        y10 = h10 * m10;
        y11 = h11 * m11;
    };

    auto step2 = [&](float a0, float a1) {
        float g0 = fmaf(a0, w2i[0],  fmaf(a1, w2i[1],  fmaf(h20, w2h[0],  fmaf(h21, w2h[1],  bb2[0]))));
        float g1 = fmaf(a0, w2i[2],  fmaf(a1, w2i[3],  fmaf(h20, w2h[2],  fmaf(h21, w2h[3],  bb2[1]))));
        float g2 = fmaf(a0, w2i[4],  fmaf(a1, w2i[5],  fmaf(h20, w2h[4],  fmaf(h21, w2h[5],  bb2[2]))));
        float g3 = fmaf(a0, w2i[6],  fmaf(a1, w2i[7],  fmaf(h20, w2h[6],  fmaf(h21, w2h[7],  bb2[3]))));
        float g4 = fmaf(a0, w2i[8],  fmaf(a1, w2i[9],  fmaf(h20, w2h[8],  fmaf(h21, w2h[9],  bb2[4]))));
        float g5 = fmaf(a0, w2i[10], fmaf(a1, w2i[11], fmaf(h20, w2h[10], fmaf(h21, w2h[11], bb2[5]))));
        float g6 = fmaf(a0, w2i[12], fmaf(a1, w2i[13], fmaf(h20, w2h[12], fmaf(h21, w2h[13], bb2[6]))));
        float g7 = fmaf(a0, w2i[14], fmaf(a1, w2i[15], fmaf(h20, w2h[14], fmaf(h21, w2h[15], bb2[7]))));
        float i0 = fsigp(g0), i1 = fsigp(g1);
        float f0 = fsigp(g2), f1 = fsigp(g3);
        float t0 = ftanh(g4), t1 = ftanh(g5);
        float o0 = fsigp(g6), o1 = fsigp(g7);
        c20 = fmaf(f0, c20, i0 * t0);
        c21 = fmaf(f1, c21, i1 * t1);
        h20 = o0 * ftanh(c20);
        h21 = o1 * ftanh(c21);
        y20 = h20 * m20;
        y21 = h21 * m21;
    };

    auto step3 = [&](float a0, float a1) -> float {
        float g0 = fmaf(a0, w3i[0], fmaf(a1, w3i[1], fmaf(h3, w3h[0], bb3[0])));
        float g1 = fmaf(a0, w3i[2], fmaf(a1, w3i[3], fmaf(h3, w3h[1], bb3[1])));
        float g2 = fmaf(a0, w3i[4], fmaf(a1, w3i[5], fmaf(h3, w3h[2], bb3[2])));
        float g3 = fmaf(a0, w3i[6], fmaf(a1, w3i[7], fmaf(h3, w3h[3], bb3[3])));
        float ig = fsigp(g0), fg = fsigp(g1), gg = ftanh(g2), og = fsigp(g3);
        c3 = fmaf(fg, c3, ig * gg);
        h3 = og * ftanh(c3);
        return h3 * m30;
    };

    const float* xp = x + b;
    float* op = out + b;
    const long long Bs = (long long)B;

    // ---- pipeline prologue ----
    step1(xp[0]);
    {
        float a0 = y10, a1 = y11;
        step1(xp[Bs]);
        step2(a0, a1);
    }

    // ---- steady state: u = 2 .. T-1; layer1(u), layer2(u-1), layer3(u-2) ----
    float xa = xp[2 * Bs], xb = xp[3 * Bs], xc = xp[4 * Bs], xd = xp[5 * Bs];

#define PIPE_SUB(XREG, OFF, ROFF)                                              \
    {                                                                          \
        float a20 = y10, a21 = y11, a30 = y20, a31 = y21;                      \
        float nx = ((u + (ROFF)) < T) ? xp[(long long)(u + (ROFF)) * Bs] : 0.f;\
        step1(XREG);                                                           \
        step2(a20, a21);                                                       \
        op[(long long)(u + (OFF) - 2) * Bs] = step3(a30, a31);                 \
        XREG = nx;                                                             \
    }

    int u = 2;
    for (; u + 3 < T; u += 4) {
        PIPE_SUB(xa, 0, 4)
        PIPE_SUB(xb, 1, 5)
        PIPE_SUB(xc, 2, 6)
        PIPE_SUB(xd, 3, 7)
    }
    for (; u < T; ++u) {
        float a20 = y10, a21 = y11, a30 = y20, a31 = y21;
        step1(xa);
        step2(a20, a21);
        op[(long long)(u - 2) * Bs] = step3(a30, a31);
        xa = xb; xb = xc; xc = xd;
    }
#undef PIPE_SUB

    // ---- epilogue ----
    {
        float a30 = y20, a31 = y21;
        step2(y10, y11);
        op[(long long)(T - 2) * Bs] = step3(a30, a31);
    }
    op[(long long)(T - 1) * Bs] = step3(y20, y21);
}

extern "C" void kernel_launch(void* const* d_in, const int* in_sizes, int n_in,
                              void* d_out, int out_size)
{
    const float* x    = (const float*)d_in[0];
    const float* W1ih = (const float*)d_in[1];
    const float* W1hh = (const float*)d_in[2];
    const float* b1   = (const float*)d_in[3];
    const float* m1   = (const float*)d_in[4];
    const float* W2ih = (const float*)d_in[5];
    const float* W2hh = (const float*)d_in[6];
    const float* b2   = (const float*)d_in[7];
    const float* m2   = (const float*)d_in[8];
    const float* W3ih = (const float*)d_in[9];
    const float* W3hh = (const float*)d_in[10];
    const float* b3   = (const float*)d_in[11];
    const float* m3   = (const float*)d_in[12];

    int B = in_sizes[12];            // m3 is [B]
    int T = in_sizes[0] / B;         // x is [T, B, 1]

    int threads = 64;
    int blocks = (B + threads - 1) / threads;
    vdlstm_kernel<<<blocks, threads>>>(x, W1ih, W1hh, b1, m1,
                                       W2ih, W2hh, b2, m2,
                                       W3ih, W3hh, b3, m3,
                                       (float*)d_out, T, B);
}